// round 2
// baseline (speedup 1.0000x reference)
#include <cuda_runtime.h>
#include <cstdint>

#define N_NODES 2048
#define FDIM 256
#define HID 64
#define TEMPLATE 10
// number of upper-triangular (k=1) pairs
#define NPAIRS (N_NODES*(N_NODES-1)/2)

// -------- scratch (static device globals; no allocation) --------
__device__ float g_h3[FDIM];
__device__ float g_pa[N_NODES * HID];   // trig @ ew1[:256]  (+ eb1 folded in)
__device__ float g_pb[N_NODES * HID];   // trig @ ew1[256:]

// =====================================================================
// Kernel A: proto mean + 3-layer GCN collapsed to a single row.
// A @ X is identity for identical rows, so the whole GCN is one vector.
// One block of 256 threads.
// =====================================================================
__global__ void gcn_kernel(const float* __restrict__ cf,
                           const int*   __restrict__ sel,
                           const float* __restrict__ w1, const float* __restrict__ b1,
                           const float* __restrict__ w2, const float* __restrict__ b2,
                           const float* __restrict__ w3, const float* __restrict__ b3) {
    __shared__ float proto[FDIM];
    __shared__ float h1[HID];
    __shared__ float h2[HID];
    int t = threadIdx.x;  // 0..255

    // proto = mean over TEMPLATE selected rows
    float s = 0.f;
    #pragma unroll
    for (int q = 0; q < TEMPLATE; q++) {
        s += cf[(size_t)sel[q] * FDIM + t];
    }
    proto[t] = s * (1.0f / TEMPLATE);
    __syncthreads();

    // h1 = relu(proto @ w1 + b1)   (256 -> 64)
    if (t < HID) {
        float a = b1[t];
        #pragma unroll 8
        for (int k = 0; k < FDIM; k++) a = fmaf(proto[k], w1[k * HID + t], a);
        h1[t] = fmaxf(a, 0.f);
    }
    __syncthreads();

    // h2 = relu(h1 @ w2 + b2)      (64 -> 64)
    if (t < HID) {
        float a = b2[t];
        #pragma unroll 8
        for (int k = 0; k < HID; k++) a = fmaf(h1[k], w2[k * HID + t], a);
        h2[t] = fmaxf(a, 0.f);
    }
    __syncthreads();

    // h3 = sigmoid(h2 @ w3 + b3)   (64 -> 256)
    {
        float a = b3[t];
        #pragma unroll 8
        for (int k = 0; k < HID; k++) a = fmaf(h2[k], w3[k * FDIM + t], a);
        g_h3[t] = 1.0f / (1.0f + __expf(-a));
    }
}

// =====================================================================
// Kernel B: build trig rows (write to out), and pa/pb = trig @ ew1 halves.
// grid = 2048 blocks (one row each), 256 threads.
// eb1 is folded into pa so the pair kernel does relu(pa+pb).
// =====================================================================
__global__ __launch_bounds__(256) void trig_pab_kernel(const float* __restrict__ noise,
                                                       const float* __restrict__ ew1,
                                                       const float* __restrict__ eb1,
                                                       float* __restrict__ trig_out) {
    __shared__ float ts[FDIM];
    int r = blockIdx.x;
    int t = threadIdx.x;

    float v = g_h3[t];
    if (r >= TEMPLATE) v = fmaf(0.1f, noise[(size_t)(r - TEMPLATE) * FDIM + t], v);
    ts[t] = v;
    trig_out[(size_t)r * FDIM + t] = v;
    __syncthreads();

    if (t < 128) {
        int half = t >> 6;       // 0 -> pa, 1 -> pb
        int o    = t & 63;
        const float* w = ew1 + (size_t)half * FDIM * HID + o;
        float a = (half == 0) ? eb1[o] : 0.f;
        #pragma unroll 8
        for (int k = 0; k < FDIM; k++) a = fmaf(ts[k], w[(size_t)k * HID], a);
        if (half == 0) g_pa[r * HID + o] = a;
        else           g_pb[r * HID + o] = a;
    }
}

// =====================================================================
// Kernel C: pairwise edge MLP over the upper triangle.
// Tile 64x64 pairs per block, 256 threads, 4x4 micro-tile per thread.
// =====================================================================
__device__ __forceinline__ float sigmoid_fast(float x) {
    float t;
    asm("tanh.approx.f32 %0, %1;" : "=f"(t) : "f"(0.5f * x));
    return fmaf(0.5f, t, 0.5f);
}

#define TILE 64
#define PADK 68   // padded k-stride: conflict-free float4 LDS

__global__ __launch_bounds__(256) void edge_kernel(const float* __restrict__ ew2,
                                                   const float* __restrict__ eb2,
                                                   float* __restrict__ out) {
    int bi = blockIdx.y;
    int bj = blockIdx.x;
    if (bi > bj) return;   // only upper-triangular tiles

    __shared__ float pa_s[TILE][PADK];
    __shared__ float pb_s[TILE][PADK];
    __shared__ float w2_s[HID];

    int tid = threadIdx.x;

    const float* paG = g_pa + bi * TILE * HID;
    const float* pbG = g_pb + bj * TILE * HID;
    #pragma unroll
    for (int it = 0; it < 4; it++) {
        int idx = tid + it * 256;          // 0..1023 float4s
        int row = idx >> 4;                // 16 float4 per row
        int kq  = (idx & 15) << 2;
        float4 va = *(const float4*)(paG + row * HID + kq);
        pa_s[row][kq] = va.x; pa_s[row][kq+1] = va.y; pa_s[row][kq+2] = va.z; pa_s[row][kq+3] = va.w;
        float4 vb = *(const float4*)(pbG + row * HID + kq);
        pb_s[row][kq] = vb.x; pb_s[row][kq+1] = vb.y; pb_s[row][kq+2] = vb.z; pb_s[row][kq+3] = vb.w;
    }
    if (tid < HID) w2_s[tid] = ew2[tid];
    float c0 = eb2[0];
    __syncthreads();

    int tx = tid & 15;   // j-direction
    int ty = tid >> 4;   // i-direction

    float acc[4][4];
    #pragma unroll
    for (int r = 0; r < 4; r++)
        #pragma unroll
        for (int c = 0; c < 4; c++) acc[r][c] = 0.f;

    #pragma unroll 4
    for (int kq = 0; kq < HID; kq += 4) {
        float4 w4 = *(const float4*)&w2_s[kq];
        float4 A0 = *(const float4*)&pa_s[ty     ][kq];
        float4 A1 = *(const float4*)&pa_s[ty + 16][kq];
        float4 A2 = *(const float4*)&pa_s[ty + 32][kq];
        float4 A3 = *(const float4*)&pa_s[ty + 48][kq];
        float4 B0 = *(const float4*)&pb_s[tx     ][kq];
        float4 B1 = *(const float4*)&pb_s[tx + 16][kq];
        float4 B2 = *(const float4*)&pb_s[tx + 32][kq];
        float4 B3 = *(const float4*)&pb_s[tx + 48][kq];

#define EDGE_STEP(COMP)                                                          \
        {                                                                        \
            float a0 = A0.COMP, a1 = A1.COMP, a2 = A2.COMP, a3 = A3.COMP;        \
            float b0 = B0.COMP, b1 = B1.COMP, b2 = B2.COMP, b3 = B3.COMP;        \
            float w  = w4.COMP;                                                  \
            acc[0][0] = fmaf(fmaxf(a0 + b0, 0.f), w, acc[0][0]);                 \
            acc[0][1] = fmaf(fmaxf(a0 + b1, 0.f), w, acc[0][1]);                 \
            acc[0][2] = fmaf(fmaxf(a0 + b2, 0.f), w, acc[0][2]);                 \
            acc[0][3] = fmaf(fmaxf(a0 + b3, 0.f), w, acc[0][3]);                 \
            acc[1][0] = fmaf(fmaxf(a1 + b0, 0.f), w, acc[1][0]);                 \
            acc[1][1] = fmaf(fmaxf(a1 + b1, 0.f), w, acc[1][1]);                 \
            acc[1][2] = fmaf(fmaxf(a1 + b2, 0.f), w, acc[1][2]);                 \
            acc[1][3] = fmaf(fmaxf(a1 + b3, 0.f), w, acc[1][3]);                 \
            acc[2][0] = fmaf(fmaxf(a2 + b0, 0.f), w, acc[2][0]);                 \
            acc[2][1] = fmaf(fmaxf(a2 + b1, 0.f), w, acc[2][1]);                 \
            acc[2][2] = fmaf(fmaxf(a2 + b2, 0.f), w, acc[2][2]);                 \
            acc[2][3] = fmaf(fmaxf(a2 + b3, 0.f), w, acc[2][3]);                 \
            acc[3][0] = fmaf(fmaxf(a3 + b0, 0.f), w, acc[3][0]);                 \
            acc[3][1] = fmaf(fmaxf(a3 + b1, 0.f), w, acc[3][1]);                 \
            acc[3][2] = fmaf(fmaxf(a3 + b2, 0.f), w, acc[3][2]);                 \
            acc[3][3] = fmaf(fmaxf(a3 + b3, 0.f), w, acc[3][3]);                 \
        }
        EDGE_STEP(x)
        EDGE_STEP(y)
        EDGE_STEP(z)
        EDGE_STEP(w)
#undef EDGE_STEP
    }

    int ibase = bi * TILE;
    int jbase = bj * TILE;
    #pragma unroll
    for (int r = 0; r < 4; r++) {
        int i = ibase + ty + r * 16;
        // linear index of pair (i,j), row-major upper triangle (k=1):
        //   m = i*(N-1) - i*(i-1)/2 + (j - i - 1)
        int off = i * (N_NODES - 1) - ((i * (i - 1)) >> 1) - i - 1;
        #pragma unroll
        for (int c = 0; c < 4; c++) {
            int j = jbase + tx + c * 16;
            if (j > i) {
                out[off + j] = sigmoid_fast(acc[r][c] + c0);
            }
        }
    }
}

// =====================================================================
// Launch
// =====================================================================
extern "C" void kernel_launch(void* const* d_in, const int* in_sizes, int n_in,
                              void* d_out, int out_size) {
    const float* clean_features = (const float*)d_in[0];
    const int*   selected_nodes = (const int*)  d_in[1];
    const float* noise          = (const float*)d_in[2];
    const float* gcn1_w         = (const float*)d_in[3];
    const float* gcn1_b         = (const float*)d_in[4];
    const float* gcn2_w         = (const float*)d_in[5];
    const float* gcn2_b         = (const float*)d_in[6];
    const float* gcn3_w         = (const float*)d_in[7];
    const float* gcn3_b         = (const float*)d_in[8];
    const float* ew1            = (const float*)d_in[9];
    const float* eb1            = (const float*)d_in[10];
    const float* ew2            = (const float*)d_in[11];
    const float* eb2            = (const float*)d_in[12];

    float* out = (float*)d_out;
    float* trig_out  = out;                      // [2048, 256]
    float* edge_out  = out + N_NODES * FDIM;     // [NPAIRS]

    gcn_kernel<<<1, 256>>>(clean_features, selected_nodes,
                           gcn1_w, gcn1_b, gcn2_w, gcn2_b, gcn3_w, gcn3_b);

    trig_pab_kernel<<<N_NODES, 256>>>(noise, ew1, eb1, trig_out);

    dim3 grid(N_NODES / TILE, N_NODES / TILE);   // 32 x 32, lower half early-exits
    edge_kernel<<<grid, 256>>>(ew2, eb2, edge_out);
}

// round 3
// speedup vs baseline: 1.1861x; 1.1861x over previous
#include <cuda_runtime.h>
#include <cstdint>

#define N_NODES 2048
#define FDIM 256
#define HID 64
#define TEMPLATE 10

// -------- scratch (static device globals; no allocation) --------
__device__ float g_h3[FDIM];
// transposed projections: [k][node]  (k = 0..63, node = 0..2047)
__device__ float g_paT[HID * N_NODES];   // trig @ ew1[:256], eb1 folded in
__device__ float g_pbT[HID * N_NODES];   // trig @ ew1[256:]

// =====================================================================
// packed f32x2 helpers (Blackwell FFMA2 path)
// =====================================================================
typedef unsigned long long u64;

__device__ __forceinline__ u64 pack2(float lo, float hi) {
    u64 r;
    asm("mov.b64 %0, {%1, %2};" : "=l"(r) : "f"(lo), "f"(hi));
    return r;
}
__device__ __forceinline__ u64 add2(u64 a, u64 b) {
    u64 r;
    asm("add.rn.f32x2 %0, %1, %2;" : "=l"(r) : "l"(a), "l"(b));
    return r;
}
__device__ __forceinline__ u64 fma2(u64 a, u64 b, u64 c) {
    u64 r;
    asm("fma.rn.f32x2 %0, %1, %2, %3;" : "=l"(r) : "l"(a), "l"(b), "l"(c));
    return r;
}
// relu on both 32-bit halves; mov.b64 pack/unpack of register pairs is
// normally elided by ptxas (register-pair aliasing).
__device__ __forceinline__ u64 relu2(u64 x) {
    u64 r;
    asm("{\n\t"
        ".reg .f32 lo, hi;\n\t"
        "mov.b64 {lo, hi}, %1;\n\t"
        "max.f32 lo, lo, 0f00000000;\n\t"
        "max.f32 hi, hi, 0f00000000;\n\t"
        "mov.b64 %0, {lo, hi};\n\t"
        "}" : "=l"(r) : "l"(x));
    return r;
}
__device__ __forceinline__ float sigmoid_fast(float x) {
    float t;
    asm("tanh.approx.f32 %0, %1;" : "=f"(t) : "f"(0.5f * x));
    return fmaf(0.5f, t, 0.5f);
}

// =====================================================================
// Kernel A: proto mean + collapsed GCN (A@X is identity for identical rows).
// One block, 256 threads; split-K + multi-accumulator for MLP.
// =====================================================================
__global__ __launch_bounds__(256) void gcn_kernel(
        const float* __restrict__ cf,  const int* __restrict__ sel,
        const float* __restrict__ w1, const float* __restrict__ b1,
        const float* __restrict__ w2, const float* __restrict__ b2,
        const float* __restrict__ w3, const float* __restrict__ b3) {
    __shared__ float proto[FDIM];
    __shared__ float red[4][HID];
    __shared__ float h1[HID];
    __shared__ float h2[HID];
    int t = threadIdx.x;  // 0..255

    // proto = mean over TEMPLATE selected rows (coalesced per row)
    {
        float s = 0.f;
        #pragma unroll
        for (int q = 0; q < TEMPLATE; q++)
            s += cf[(size_t)sel[q] * FDIM + t];
        proto[t] = s * (1.0f / TEMPLATE);
    }
    __syncthreads();

    // layer1: 256 -> 64.  o = t&63 (output), kq = t>>6 (k-quarter, 64 k's)
    {
        int o = t & 63, kq = t >> 6;
        const float* w = w1 + (size_t)(kq * 64) * HID + o;
        const float* p = proto + kq * 64;
        float a0 = 0.f, a1 = 0.f, a2 = 0.f, a3 = 0.f;
        #pragma unroll
        for (int k = 0; k < 64; k += 4) {
            a0 = fmaf(p[k],     w[(k)     * HID], a0);
            a1 = fmaf(p[k + 1], w[(k + 1) * HID], a1);
            a2 = fmaf(p[k + 2], w[(k + 2) * HID], a2);
            a3 = fmaf(p[k + 3], w[(k + 3) * HID], a3);
        }
        red[kq][o] = (a0 + a1) + (a2 + a3);
    }
    __syncthreads();
    if (t < HID)
        h1[t] = fmaxf(red[0][t] + red[1][t] + red[2][t] + red[3][t] + b1[t], 0.f);
    __syncthreads();

    // layer2: 64 -> 64.  16 k's per thread
    {
        int o = t & 63, kq = t >> 6;
        const float* w = w2 + (size_t)(kq * 16) * HID + o;
        const float* p = h1 + kq * 16;
        float a0 = 0.f, a1 = 0.f;
        #pragma unroll
        for (int k = 0; k < 16; k += 2) {
            a0 = fmaf(p[k],     w[(k)     * HID], a0);
            a1 = fmaf(p[k + 1], w[(k + 1) * HID], a1);
        }
        red[kq][o] = a0 + a1;
    }
    __syncthreads();
    if (t < HID)
        h2[t] = fmaxf(red[0][t] + red[1][t] + red[2][t] + red[3][t] + b2[t], 0.f);
    __syncthreads();

    // layer3: 64 -> 256, one output per thread, 4 accumulators
    {
        const float* w = w3 + t;
        float a0 = 0.f, a1 = 0.f, a2 = 0.f, a3 = 0.f;
        #pragma unroll
        for (int k = 0; k < HID; k += 4) {
            a0 = fmaf(h2[k],     w[(size_t)(k)     * FDIM], a0);
            a1 = fmaf(h2[k + 1], w[(size_t)(k + 1) * FDIM], a1);
            a2 = fmaf(h2[k + 2], w[(size_t)(k + 2) * FDIM], a2);
            a3 = fmaf(h2[k + 3], w[(size_t)(k + 3) * FDIM], a3);
        }
        float a = (a0 + a1) + (a2 + a3) + b3[t];
        g_h3[t] = 1.0f / (1.0f + __expf(-a));
    }
}

// =====================================================================
// Kernel B: build trig rows (to out), compute pa/pb = trig @ ew1 halves,
// store TRANSPOSED (g_paT/g_pbT[k][node]) for the edge kernel.
// 8 rows per block, 256 blocks, 256 threads. eb1 folded into paT.
// =====================================================================
#define RPB 8

__global__ __launch_bounds__(256) void trig_pab_kernel(
        const float* __restrict__ noise,
        const float* __restrict__ ew1,
        const float* __restrict__ eb1,
        float* __restrict__ trig_out) {
    __shared__ float ts[RPB][FDIM];          // 8 KB
    __shared__ float part[2][RPB][128];      // 8 KB
    int b = blockIdx.x, t = threadIdx.x;
    int r0 = b * RPB;

    float h3v = g_h3[t];
    #pragma unroll
    for (int rr = 0; rr < RPB; rr++) {
        int r = r0 + rr;
        float v = h3v;
        if (r >= TEMPLATE) v = fmaf(0.1f, noise[(size_t)(r - TEMPLATE) * FDIM + t], v);
        ts[rr][t] = v;
        trig_out[(size_t)r * FDIM + t] = v;
    }
    __syncthreads();

    // o = t & 127 (0..63 -> pa col o, 64..127 -> pb col o-64), kh = t >> 7
    int o = t & 127, kh = t >> 7;
    int half = o >> 6;
    int oc = o & 63;
    const float* w = ew1 + ((size_t)half * FDIM + kh * 128) * HID + oc;
    const float* p = &ts[0][kh * 128];

    float acc[RPB];
    #pragma unroll
    for (int rr = 0; rr < RPB; rr++) acc[rr] = 0.f;

    #pragma unroll 4
    for (int k = 0; k < 128; k++) {
        float wv = w[(size_t)k * HID];
        #pragma unroll
        for (int rr = 0; rr < RPB; rr++)
            acc[rr] = fmaf(p[rr * FDIM + k], wv, acc[rr]);
    }
    #pragma unroll
    for (int rr = 0; rr < RPB; rr++) part[kh][rr][o] = acc[rr];
    __syncthreads();

    // finalize: 8 rows x 128 cols, transpose-store to g_paT/g_pbT[k][node]
    #pragma unroll
    for (int i = t; i < RPB * 128; i += 256) {
        int rr = i >> 7, oo = i & 127;
        float v = part[0][rr][oo] + part[1][rr][oo];
        int hh = oo >> 6, c = oo & 63;
        int node = r0 + rr;
        if (hh == 0) g_paT[(size_t)c * N_NODES + node] = v + eb1[c];
        else         g_pbT[(size_t)c * N_NODES + node] = v;
    }
}

// =====================================================================
// Kernel C: pairwise edge MLP over the upper triangle, packed f32x2.
// 64x64 tile per block, 128 threads, per-thread 4 i x 8 j (4 packed pairs).
// =====================================================================
#define TILE 64
#define PADK 68

__global__ __launch_bounds__(128) void edge_kernel(
        const float* __restrict__ ew2,
        const float* __restrict__ eb2,
        float* __restrict__ out) {
    int bi = blockIdx.y;
    int bj = blockIdx.x;
    if (bj < bi) return;    // need j > i

    __shared__ float paT_s[HID][PADK];   // [k][i], 17.4 KB
    __shared__ float pbT_s[HID][PADK];   // [k][j], 17.4 KB
    __shared__ float w2_s[HID];

    int tid = threadIdx.x;

    // load tiles (coalesced: g_paT rows are node-contiguous)
    {
        const float* paG = g_paT + bi * TILE;
        const float* pbG = g_pbT + bj * TILE;
        #pragma unroll
        for (int it = 0; it < 8; it++) {
            int idx = tid + it * 128;          // 0..1023 float4 slots
            int k   = idx >> 4;                // 16 float4 per row of 64
            int c4  = (idx & 15) << 2;
            float4 va = *(const float4*)(paG + (size_t)k * N_NODES + c4);
            *(float4*)&paT_s[k][c4] = va;
            float4 vb = *(const float4*)(pbG + (size_t)k * N_NODES + c4);
            *(float4*)&pbT_s[k][c4] = vb;
        }
        if (tid < HID) w2_s[tid] = ew2[tid];
    }
    float c0 = eb2[0];
    __syncthreads();

    int tx = tid & 7;    // j-group: j = 8*tx .. 8*tx+7
    int ty = tid >> 3;   // i-group: i = 4*ty .. 4*ty+3

    u64 acc[4][4];
    #pragma unroll
    for (int r = 0; r < 4; r++)
        #pragma unroll
        for (int p = 0; p < 4; p++) acc[r][p] = 0ull;

    #pragma unroll 2
    for (int k = 0; k < HID; k++) {
        float wk = w2_s[k];
        u64 ww = pack2(wk, wk);
        float4 av = *(const float4*)&paT_s[k][4 * ty];
        ulonglong2 b01 = *(const ulonglong2*)&pbT_s[k][8 * tx];
        ulonglong2 b23 = *(const ulonglong2*)&pbT_s[k][8 * tx + 4];
        u64 ad[4];
        ad[0] = pack2(av.x, av.x);
        ad[1] = pack2(av.y, av.y);
        ad[2] = pack2(av.z, av.z);
        ad[3] = pack2(av.w, av.w);
        u64 bb[4] = { b01.x, b01.y, b23.x, b23.y };
        #pragma unroll
        for (int r = 0; r < 4; r++) {
            #pragma unroll
            for (int p = 0; p < 4; p++) {
                u64 x = relu2(add2(ad[r], bb[p]));
                acc[r][p] = fma2(x, ww, acc[r][p]);
            }
        }
    }

    int ibase = bi * TILE;
    int jbase = bj * TILE;
    #pragma unroll
    for (int r = 0; r < 4; r++) {
        int i = ibase + 4 * ty + r;
        // linear index of (i,j) in row-major upper triangle (k=1):
        //   m = i*(N-1) - i*(i-1)/2 + (j - i - 1)
        int off = i * (N_NODES - 1) - ((i * (i - 1)) >> 1) - i - 1;
        #pragma unroll
        for (int p = 0; p < 4; p++) {
            int j0 = jbase + 8 * tx + 2 * p;
            float lo = __uint_as_float((unsigned)(acc[r][p] & 0xffffffffull));
            float hi = __uint_as_float((unsigned)(acc[r][p] >> 32));
            if (j0     > i) out[off + j0]     = sigmoid_fast(lo + c0);
            if (j0 + 1 > i) out[off + j0 + 1] = sigmoid_fast(hi + c0);
        }
    }
}

// =====================================================================
// Launch
// =====================================================================
extern "C" void kernel_launch(void* const* d_in, const int* in_sizes, int n_in,
                              void* d_out, int out_size) {
    const float* clean_features = (const float*)d_in[0];
    const int*   selected_nodes = (const int*)  d_in[1];
    const float* noise          = (const float*)d_in[2];
    const float* gcn1_w         = (const float*)d_in[3];
    const float* gcn1_b         = (const float*)d_in[4];
    const float* gcn2_w         = (const float*)d_in[5];
    const float* gcn2_b         = (const float*)d_in[6];
    const float* gcn3_w         = (const float*)d_in[7];
    const float* gcn3_b         = (const float*)d_in[8];
    const float* ew1            = (const float*)d_in[9];
    const float* eb1            = (const float*)d_in[10];
    const float* ew2            = (const float*)d_in[11];
    const float* eb2            = (const float*)d_in[12];

    float* out = (float*)d_out;
    float* trig_out = out;                    // [2048, 256]
    float* edge_out = out + N_NODES * FDIM;   // [2096128]

    gcn_kernel<<<1, 256>>>(clean_features, selected_nodes,
                           gcn1_w, gcn1_b, gcn2_w, gcn2_b, gcn3_w, gcn3_b);

    trig_pab_kernel<<<N_NODES / RPB, 256>>>(noise, ew1, eb1, trig_out);

    dim3 grid(N_NODES / TILE, N_NODES / TILE);   // 32 x 32, lower half exits
    edge_kernel<<<grid, 128>>>(ew2, eb2, edge_out);
}